// round 8
// baseline (speedup 1.0000x reference)
#include <cuda_runtime.h>
#include <cstdint>

// Problem constants
#define SIG_HW   256
#define CIN      64
#define COUT     64
#define KS       31
#define PADK     15
#define NBATCH   8
#define XT       128

// smem geometry (per CTA): signal 2 rows x 64c x 160 (swizzled) + 2 weight tiles
#define SA_STRIDE 160
#define ROW_ELEMS (CIN * SA_STRIDE)            // 10240 floats
#define SW_ELEMS  (COUT * 64)                  // 4096 floats per tile (swizzled, no pad)
#define SMEM_FLOATS (2 * ROW_ELEMS + 2 * SW_ELEMS)   // 28672 floats = 114688 B

__device__ float g_w2[KS * KS * COUT * CIN];

__device__ __forceinline__ unsigned f2tf(float x) {
    unsigned r;
    asm("cvt.rna.tf32.f32 %0, %1;" : "=r"(r) : "f"(x));
    return r;
}

__device__ __forceinline__ uint32_t s2u(const void* p) {
    uint32_t a;
    asm("{ .reg .u64 t; cvta.to.shared.u64 t, %1; cvt.u32.u64 %0, t; }" : "=r"(a) : "l"(p));
    return a;
}

// ---------------------------------------------------------------------------
// Pre-kernel: w[o][c][ky][kx] (fp32) -> g_w2[((ky*31+kx)*64 + o)*64 + c] (tf32)
// ---------------------------------------------------------------------------
__global__ void prep_weights(const float* __restrict__ w) {
    int idx = blockIdx.x * 256 + threadIdx.x;
    if (idx >= KS * KS * COUT * CIN) return;
    int kx = idx % KS;
    int t  = idx / KS;
    int ky = t % KS;  t /= KS;
    int c  = t % CIN;
    int o  = t / CIN;
    unsigned v = f2tf(w[idx]);
    g_w2[((ky * KS + kx) * COUT + o) * CIN + c] = __uint_as_float(v);
}

__device__ __forceinline__ void mma_tf32(float* d, const unsigned* a,
                                         unsigned b0, unsigned b1) {
    asm volatile(
        "mma.sync.aligned.m16n8k8.row.col.f32.tf32.tf32.f32 "
        "{%0,%1,%2,%3}, {%4,%5,%6,%7}, {%8,%9}, {%0,%1,%2,%3};\n"
        : "+f"(d[0]), "+f"(d[1]), "+f"(d[2]), "+f"(d[3])
        : "r"(a[0]), "r"(a[1]), "r"(a[2]), "r"(a[3]), "r"(b0), "r"(b1));
}

extern __shared__ float smem_dyn[];

// ---------------------------------------------------------------------------
// Block = (x-half, y-pair, batch). Computes out[b][0..63][y..y+1][x0..x0+127].
// 2 CTAs/SM (sync bubbles of one CTA covered by the other's MMA phase).
// 8 warps = 2 m-halves x 4 n-quarters; per warp 2 m16-tiles x 4 n8-tiles x 2y.
// Weights: cp.async double-buffer, swizzled stride-64 (bank-conflict-free
// A-frags via col' = (c + 4*(o&7)) % 64).
// Signal: 2-row ring, swizzled stride-160 (col' = (j + 8*(c&3)) % 160).
// ---------------------------------------------------------------------------
__global__ void __launch_bounds__(256, 2) conv_main(
    const float* __restrict__ sig,
    const float* __restrict__ bias,
    float* __restrict__ out)
{
    float* sA = smem_dyn;                       // [2][CIN][160] signal ring
    float* sW = smem_dyn + 2 * ROW_ELEMS;       // [2][64][64] weight tiles
    const uint32_t swu = s2u(sW);

    const int tid  = threadIdx.x;
    const int lane = tid & 31;
    const int warp = tid >> 5;
    const int wm   = warp >> 2;      // m-half (o 0-31 / 32-63)
    const int wn   = warp & 3;       // n-quarter (32 x each)
    const int g    = lane >> 2;      // groupID
    const int t4   = lane & 3;       // thread-in-group
    const int bx   = blockIdx.x;
    const int xh   = bx & 1;
    const int y    = (bx >> 1) * 2;
    const int b    = blockIdx.y;
    const int x0   = xh * XT;

    float acc[2][4][8];              // [mt][nt][y01*4 + frag]
#pragma unroll
    for (int mt = 0; mt < 2; mt++)
#pragma unroll
        for (int nt = 0; nt < 4; nt++)
#pragma unroll
            for (int r = 0; r < 8; r++) acc[mt][nt][r] = 0.f;

    const float* sigb = sig + ((long)b << 22);

    // signal row loader: row j (0..31), iy = y-15+j -> ring slot j&1 (swizzled)
    auto load_row = [&](int j) {
        const int iy = y - PADK + j;
        const bool vy = (iy >= 0 && iy < SIG_HW);
        const int c  = tid >> 2;
        const int q4 = tid & 3;
        const float* src = sigb + ((long)c << 16) + ((long)iy << 8);
        float* dst = sA + (j & 1) * ROW_ELEMS + c * SA_STRIDE;
        const int perm = (c & 3) << 3;
#pragma unroll
        for (int jj = q4; jj < XT + KS - 1; jj += 4) {
            const int ix = x0 + jj - PADK;
            float v = (vy && ix >= 0 && ix < SIG_HW) ? __ldg(src + ix) : 0.f;
            int col = jj + perm;
            if (col >= SA_STRIDE) col -= SA_STRIDE;
            dst[col] = __uint_as_float(f2tf(v));
        }
    };

    // weight tile q -> smem buffer q&1 via cp.async (swizzled)
    auto issue_w = [&](int q) {
        const float4* src = (const float4*)g_w2 + (size_t)q * 1024;
        const uint32_t base = swu + (uint32_t)(q & 1) * (SW_ELEMS * 4);
#pragma unroll
        for (int i = 0; i < 4; i++) {
            const int e  = i * 256 + tid;
            const int o  = e >> 4;
            const int c4 = (e & 15) << 2;
            const int c4p = (c4 + ((o & 7) << 2)) & 63;
            const uint32_t dstu = base + (uint32_t)((o << 6) + c4p) * 4u;
            asm volatile("cp.async.cg.shared.global [%0], [%1], 16;"
                         :: "r"(dstu), "l"(src + e) : "memory");
        }
    };

    // prologue: row 0 + weight tile 0 in flight
    load_row(0);
    issue_w(0);
    asm volatile("cp.async.commit_group;" ::: "memory");

    const int colA_base = t4 + (g << 2);          // A swizzle base (distinct banks)
    const int bcolbase  = wn * 32 + g + (t4 << 3); // B col base incl swizzle perm

    for (int t = 0; t < KS; t++) {
        const float* A0 = sA + (t & 1) * ROW_ELEMS;        // row t   (output y)
        const float* A1 = sA + ((t + 1) & 1) * ROW_ELEMS;  // row t+1 (output y+1)
        for (int kx = 0; kx < KS; kx++) {
            const int q = t * KS + kx;
            if (kx == 0) {
                __syncthreads();      // all MMA(q-1) done -> row ring slot free
                load_row(t + 1);
            }
            asm volatile("cp.async.wait_group 0;" ::: "memory");  // tile q arrived
            __syncthreads();          // weights(q) + row(t+1) visible; MMA(q-1) done
            if (q + 1 < KS * KS) issue_w(q + 1);   // overlaps MMA(q); buf free by sync
            asm volatile("cp.async.commit_group;" ::: "memory");

            const float* wb = sW + (q & 1) * SW_ELEMS;
            int bc[4];
#pragma unroll
            for (int nt = 0; nt < 4; nt++) {
                int cc = bcolbase + kx + nt * 8;
                if (cc >= SA_STRIDE) cc -= SA_STRIDE;
                bc[nt] = cc;
            }
#pragma unroll
            for (int kc = 0; kc < 8; kc++) {
                const int cA0 = (kc * 8 + colA_base) & 63;
                const int cA1 = (cA0 + 4) & 63;
                unsigned a[2][4];
#pragma unroll
                for (int mt = 0; mt < 2; mt++) {
                    const float* pw = wb + (((wm * 2 + mt) * 16 + g) << 6);
                    a[mt][0] = __float_as_uint(pw[cA0]);
                    a[mt][1] = __float_as_uint(pw[512 + cA0]);
                    a[mt][2] = __float_as_uint(pw[cA1]);
                    a[mt][3] = __float_as_uint(pw[512 + cA1]);
                }
                const int ro = (kc * 8 + t4) * SA_STRIDE;
#pragma unroll
                for (int nt = 0; nt < 4; nt++) {
                    const unsigned b00 = __float_as_uint(A0[ro + bc[nt]]);
                    const unsigned b01 = __float_as_uint(A0[ro + 4 * SA_STRIDE + bc[nt]]);
                    const unsigned b10 = __float_as_uint(A1[ro + bc[nt]]);
                    const unsigned b11 = __float_as_uint(A1[ro + 4 * SA_STRIDE + bc[nt]]);
#pragma unroll
                    for (int mt = 0; mt < 2; mt++) {
                        mma_tf32(&acc[mt][nt][0], a[mt], b00, b01);
                        mma_tf32(&acc[mt][nt][4], a[mt], b10, b11);
                    }
                }
            }
        }
    }

    // epilogue: bias + store out[b][o][y+y01][x]
#pragma unroll
    for (int mt = 0; mt < 2; mt++) {
#pragma unroll
        for (int r = 0; r < 2; r++) {
            const int o = (wm * 2 + mt) * 16 + r * 8 + g;
            const float bv = __ldg(bias + o);
            float* obase = out + (((long)(b * COUT + o)) << 16) + ((long)y << 8)
                         + x0 + wn * 32 + t4 * 2;
#pragma unroll
            for (int y01 = 0; y01 < 2; y01++) {
                float* orow = obase + y01 * SIG_HW;
#pragma unroll
                for (int nt = 0; nt < 4; nt++) {
                    float2 v;
                    v.x = acc[mt][nt][y01 * 4 + r * 2 + 0] + bv;
                    v.y = acc[mt][nt][y01 * 4 + r * 2 + 1] + bv;
                    *(float2*)(orow + nt * 8) = v;
                }
            }
        }
    }
}

// ---------------------------------------------------------------------------
extern "C" void kernel_launch(void* const* d_in, const int* in_sizes, int n_in,
                              void* d_out, int out_size) {
    const float* sig  = (const float*)d_in[0];
    const float* w    = (const float*)d_in[1];
    const float* bias = (const float*)d_in[2];
    float* out        = (float*)d_out;

    const int wtot = KS * KS * COUT * CIN;
    prep_weights<<<(wtot + 255) / 256, 256>>>(w);

    const size_t smem_bytes = (size_t)SMEM_FLOATS * sizeof(float);  // 114688
    cudaFuncSetAttribute(conv_main, cudaFuncAttributeMaxDynamicSharedMemorySize,
                         (int)smem_bytes);
    dim3 grid(2 * (SIG_HW / 2), NBATCH);   // (x-half, y-pair) x batch = 256 x 8
    conv_main<<<grid, 256, smem_bytes>>>(sig, bias, out);
}

// round 9
// speedup vs baseline: 1.0452x; 1.0452x over previous
#include <cuda_runtime.h>
#include <cstdint>

// Problem constants
#define SIG_HW   256
#define CIN      64
#define COUT     64
#define KS       31
#define PADK     15
#define NBATCH   8

// smem geometry
#define SA_STRIDE 296   // signal row-channel stride; 296 % 32 == 8 -> conflict-free B frags
#define SW_STRIDE 68    // weight o-row stride; conflict-free A frags
#define SA_ROW_ELEMS (CIN * SA_STRIDE)            // 18944 floats per signal row tile
#define SW_TILE_ELEMS (COUT * SW_STRIDE)          // 4352 floats per weight tile
#define SMEM_FLOATS (2 * SA_ROW_ELEMS + 4 * SW_TILE_ELEMS)  // 55296 floats = 221184 B

__device__ float g_w2[KS * KS * COUT * CIN];

__device__ __forceinline__ unsigned f2tf(float x) {
    unsigned r;
    asm("cvt.rna.tf32.f32 %0, %1;" : "=r"(r) : "f"(x));
    return r;
}

__device__ __forceinline__ uint32_t s2u(const void* p) {
    uint32_t a;
    asm("{ .reg .u64 t; cvta.to.shared.u64 t, %1; cvt.u32.u64 %0, t; }" : "=r"(a) : "l"(p));
    return a;
}

// ---------------------------------------------------------------------------
// Pre-kernel: w[o][c][ky][kx] (fp32) -> g_w2[((ky*31+kx)*64 + o)*64 + c] (tf32)
// ---------------------------------------------------------------------------
__global__ void prep_weights(const float* __restrict__ w) {
    int idx = blockIdx.x * 256 + threadIdx.x;
    if (idx >= KS * KS * COUT * CIN) return;
    int kx = idx % KS;
    int t  = idx / KS;
    int ky = t % KS;  t /= KS;
    int c  = t % CIN;
    int o  = t / CIN;
    unsigned v = f2tf(w[idx]);
    g_w2[((ky * KS + kx) * COUT + o) * CIN + c] = __uint_as_float(v);
}

__device__ __forceinline__ void mma_tf32(float* d, const unsigned* a,
                                         unsigned b0, unsigned b1) {
    asm volatile(
        "mma.sync.aligned.m16n8k8.row.col.f32.tf32.tf32.f32 "
        "{%0,%1,%2,%3}, {%4,%5,%6,%7}, {%8,%9}, {%0,%1,%2,%3};\n"
        : "+f"(d[0]), "+f"(d[1]), "+f"(d[2]), "+f"(d[3])
        : "r"(a[0]), "r"(a[1]), "r"(a[2]), "r"(a[3]), "r"(b0), "r"(b1));
}

extern __shared__ float smem_dyn[];

// ---------------------------------------------------------------------------
// Block = (y-pair, batch). Computes out[b][0..63][y..y+1][0..255].
// 8 warps, each an x-slice of 32: all 4 m16-tiles x 4 n8-tiles x 2 y.
// Weight tiles double-buffered in PAIRS via cp.async (4 slots, slot=q&3):
// one wait+sync covers two (ky,kx) tiles -> 512 MMAs/warp per barrier.
// Signal: 2-row ring (row t at slot t&1), loaded at kx==0 of step t.
// ---------------------------------------------------------------------------
__global__ void __launch_bounds__(256, 1) conv_main(
    const float* __restrict__ sig,
    const float* __restrict__ bias,
    float* __restrict__ out)
{
    float* sA = smem_dyn;                       // [2][CIN][296] signal ring
    float* sW = smem_dyn + 2 * SA_ROW_ELEMS;    // [4][COUT][68] weight slots
    const uint32_t swu = s2u(sW);

    const int tid  = threadIdx.x;
    const int lane = tid & 31;
    const int warp = tid >> 5;       // x-slice of 32
    const int g    = lane >> 2;      // groupID
    const int t4   = lane & 3;       // thread-in-group
    const int y    = blockIdx.x * 2;
    const int b    = blockIdx.y;

    float acc[4][4][8];              // [mt][nt][y01*4 + frag]
#pragma unroll
    for (int mt = 0; mt < 4; mt++)
#pragma unroll
        for (int nt = 0; nt < 4; nt++)
#pragma unroll
            for (int r = 0; r < 8; r++) acc[mt][nt][r] = 0.f;

    const float* sigb = sig + ((long)b << 22);

    // signal row loader: row j (0..31), iy = y-15+j -> ring slot j&1
    auto load_row = [&](int j) {
        const int iy = y - PADK + j;
        const bool vy = (iy >= 0 && iy < SIG_HW);
        const int c  = tid >> 2;
        const int q4 = tid & 3;
        const float* src = sigb + ((long)c << 16) + ((long)iy << 8);
        float* dst = sA + (j & 1) * SA_ROW_ELEMS + c * SA_STRIDE;
#pragma unroll 6
        for (int jj = q4; jj < SIG_HW + KS - 1; jj += 4) {
            int ix = jj - PADK;
            float v = (vy && ix >= 0 && ix < SIG_HW) ? __ldg(src + ix) : 0.f;
            dst[jj] = __uint_as_float(f2tf(v));
        }
    };

    // weight tile q -> smem slot q&3 via cp.async (4 x 16B per thread)
    auto issue_w = [&](int q) {
        const float4* src = (const float4*)g_w2 + (size_t)q * 1024;
        const uint32_t base = swu + (uint32_t)(q & 3) * (SW_TILE_ELEMS * 4);
#pragma unroll
        for (int i = 0; i < 4; i++) {
            const int e  = i * 256 + tid;
            const int o  = e >> 4;
            const int c4 = (e & 15) << 2;
            const uint32_t dstu = base + (uint32_t)(o * SW_STRIDE + c4) * 4u;
            asm volatile("cp.async.cg.shared.global [%0], [%1], 16;"
                         :: "r"(dstu), "l"(src + e) : "memory");
        }
    };

    // one weight tile's worth of MMAs (both output rows)
    auto do_tile = [&](const float* wb, int kx, const float* A0, const float* A1) {
        const int colb = warp * 32 + g + kx;
#pragma unroll
        for (int kc = 0; kc < 8; kc++) {
            unsigned a[4][4];
#pragma unroll
            for (int mt = 0; mt < 4; mt++) {
                const float* p = wb + (mt * 16 + g) * SW_STRIDE + kc * 8 + t4;
                a[mt][0] = __float_as_uint(p[0]);
                a[mt][1] = __float_as_uint(p[8 * SW_STRIDE]);
                a[mt][2] = __float_as_uint(p[4]);
                a[mt][3] = __float_as_uint(p[8 * SW_STRIDE + 4]);
            }
#pragma unroll
            for (int nt = 0; nt < 4; nt++) {
                const int off = (kc * 8 + t4) * SA_STRIDE + colb + nt * 8;
                const unsigned b00 = __float_as_uint(A0[off]);
                const unsigned b01 = __float_as_uint(A0[off + 4 * SA_STRIDE]);
                const unsigned b10 = __float_as_uint(A1[off]);
                const unsigned b11 = __float_as_uint(A1[off + 4 * SA_STRIDE]);
#pragma unroll
                for (int mt = 0; mt < 4; mt++) {
                    mma_tf32(&acc[mt][nt][0], a[mt], b00, b01);
                    mma_tf32(&acc[mt][nt][4], a[mt], b10, b11);
                }
            }
        }
    };

    // prologue: row 0; pair 0 (tiles 0,1) in flight
    load_row(0);
    issue_w(0);
    issue_w(1);
    asm volatile("cp.async.commit_group;" ::: "memory");

    // pair pi = t*16 + p; tiles q0 = t*31 + 2p (+ q0+1 if p<15)
    for (int t = 0; t < KS; t++) {
        const float* A0 = sA + (t & 1) * SA_ROW_ELEMS;        // row t   (output y)
        const float* A1 = sA + ((t + 1) & 1) * SA_ROW_ELEMS;  // row t+1 (output y+1)
#pragma unroll 1
        for (int p = 0; p < 16; p++) {
            const int q0 = t * KS + 2 * p;
            const bool has2 = (p < 15);

            asm volatile("cp.async.wait_group 0;" ::: "memory");  // pair arrived
            __syncthreads();   // weights visible; prev pair's MMAs done (slots free)

            if (p == 0) load_row(t + 1);

            // issue next pair (tiles q0+1+has2, +1) into slots freed above
            {
                const int nq = q0 + (has2 ? 2 : 1);
                if (nq < KS * KS) {
                    issue_w(nq);
                    if (nq + 1 < KS * KS && ((nq % KS) != 0 ? 1 : 0) + 1 <= 2) {
                        // second tile of next pair exists unless next pair is a
                        // singleton (p==15 of its row): next pair starts at
                        // kx = nq % KS; singleton only when kx == 30
                        if ((nq % KS) != KS - 1) issue_w(nq + 1);
                    }
                    asm volatile("cp.async.commit_group;" ::: "memory");
                }
            }

            if (p == 0) __syncthreads();   // row t+1 visible before its MMAs

            do_tile(sW + (size_t)(q0 & 3) * SW_TILE_ELEMS, 2 * p, A0, A1);
            if (has2)
                do_tile(sW + (size_t)((q0 + 1) & 3) * SW_TILE_ELEMS, 2 * p + 1, A0, A1);
        }
    }

    // epilogue: bias + store out[b][o][y+y01][x]
#pragma unroll
    for (int mt = 0; mt < 4; mt++) {
#pragma unroll
        for (int r = 0; r < 2; r++) {
            const int o = mt * 16 + r * 8 + g;
            const float bv = __ldg(bias + o);
            float* obase = out + (((long)(b * COUT + o)) << 16) + ((long)y << 8)
                         + warp * 32 + t4 * 2;
#pragma unroll
            for (int y01 = 0; y01 < 2; y01++) {
                float* orow = obase + y01 * SIG_HW;
#pragma unroll
                for (int nt = 0; nt < 4; nt++) {
                    float2 v;
                    v.x = acc[mt][nt][y01 * 4 + r * 2 + 0] + bv;
                    v.y = acc[mt][nt][y01 * 4 + r * 2 + 1] + bv;
                    *(float2*)(orow + nt * 8) = v;
                }
            }
        }
    }
}

// ---------------------------------------------------------------------------
extern "C" void kernel_launch(void* const* d_in, const int* in_sizes, int n_in,
                              void* d_out, int out_size) {
    const float* sig  = (const float*)d_in[0];
    const float* w    = (const float*)d_in[1];
    const float* bias = (const float*)d_in[2];
    float* out        = (float*)d_out;

    const int wtot = KS * KS * COUT * CIN;
    prep_weights<<<(wtot + 255) / 256, 256>>>(w);

    const size_t smem_bytes = (size_t)SMEM_FLOATS * sizeof(float);  // 221184
    cudaFuncSetAttribute(conv_main, cudaFuncAttributeMaxDynamicSharedMemorySize,
                         (int)smem_bytes);
    dim3 grid(SIG_HW / 2, NBATCH);   // 128 y-pairs x 8 batches
    conv_main<<<grid, 256, smem_bytes>>>(sig, bias, out);
}

// round 13
// speedup vs baseline: 5.2339x; 5.0074x over previous
#include <cuda_runtime.h>
#include <cstdint>

// Problem constants
#define SIG_HW 256
#define CIN    64
#define COUT   64
#define KS     31
#define PADK   15
#define NBATCH 8
#define NF     257           // rfft-512 bins
#define WA_STRIDE 132        // A-tile row stride (132%32==4 -> conflict-free frags)
#define WA_ELEMS (COUT * WA_STRIDE)          // 8448 floats per (f,ky) A-tile
#define SB_STRIDE 296        // 296%32==8 -> conflict-free B frags
#define SB_ROWS  128         // c2 = [Sr(64) ; Si(64)]

// -------- device scratch (allowed: __device__ globals) --------
__device__ float g_Sr[NBATCH * NF * CIN * 256];   // [b][f][c][y]
__device__ float g_Si[NBATCH * NF * CIN * 256];
__device__ float g_wA[NF * KS * WA_ELEMS];        // [f][ky][o][c2(132)] = [Wr|Wi]
__device__ float g_Or[NF * NBATCH * COUT * 256];  // [f][b][o][y]
__device__ float g_Oi[NF * NBATCH * COUT * 256];
__device__ float g_t256r[128], g_t256i[128];      // e^{-2pi i k/256}
__device__ float g_t512r[NF],  g_t512i[NF];       // e^{-2pi i k/512}

__device__ __forceinline__ unsigned f2tf(float x) {
    unsigned r;
    asm("cvt.rna.tf32.f32 %0, %1;" : "=r"(r) : "f"(x));
    return r;
}
__device__ __forceinline__ int rev8(int n) { return (int)(__brev((unsigned)n) >> 24); }

// ---------------------------------------------------------------------------
__global__ void tw_init() {
    int k = threadIdx.x;
    if (k < 128) {
        float s, c;
        sincospif((float)k / 128.0f, &s, &c);
        g_t256r[k] = c; g_t256i[k] = -s;
    }
    if (k < NF) {
        float s, c;
        sincospif((float)k / 256.0f, &s, &c);
        g_t512r[k] = c; g_t512i[k] = -s;
    }
}

// ---------------------------------------------------------------------------
// In-smem 256-pt complex FFT, one warp, DIT radix-2, bit-reversed input order.
// twr/twi: smem copies of g_t256*.
// ---------------------------------------------------------------------------
__device__ __forceinline__ void fft256(float* fr, float* fi,
                                       const float* twr, const float* twi,
                                       int lane) {
    for (int len = 2; len <= 256; len <<= 1) {
        const int half = len >> 1;
        const int step = 256 / len;
        for (int j = lane; j < 128; j += 32) {
            const int pos  = j & (half - 1);
            const int idx0 = ((j & ~(half - 1)) << 1) + pos;
            const int idx1 = idx0 + half;
            const float wr = twr[pos * step], wi = twi[pos * step];
            const float ar1 = fr[idx1], ai1 = fi[idx1];
            const float tr = wr * ar1 - wi * ai1;
            const float ti = wr * ai1 + wi * ar1;
            const float ar0 = fr[idx0], ai0 = fi[idx0];
            fr[idx1] = ar0 - tr;  fi[idx1] = ai0 - ti;
            fr[idx0] = ar0 + tr;  fi[idx0] = ai0 + ti;
        }
        __syncwarp();
    }
}

// shared smem layout for the FFT-ish kernels (floats):
// [0:128) t256r | [128:256) t256i | [256:513) t512r | [513:770) t512i
// [770 .. 770+4096) row scratch: 8 warps x (256 re + 256 im)
// [4866 .. +8224) tsr[32][257] | then tsi[32][257]
#define FX_T256R 0
#define FX_T256I 128
#define FX_T512R 256
#define FX_T512I 513
#define FX_ROW   770
#define FX_TSR   (FX_ROW + 8 * 512)
#define FX_TSI   (FX_TSR + 32 * NF)
#define FX_TOTAL (FX_TSI + 32 * NF)          // 21314 floats = 85256 B

__device__ __forceinline__ void load_tw(float* sm, int tid) {
    for (int i = tid; i < 128; i += 256) { sm[FX_T256R + i] = g_t256r[i]; sm[FX_T256I + i] = g_t256i[i]; }
    for (int i = tid; i < NF;  i += 256) { sm[FX_T512R + i] = g_t512r[i]; sm[FX_T512I + i] = g_t512i[i]; }
}

// rfft-512 of a real row (first L samples from src, rest zero) -> ts[yloc][0..256]
__device__ __forceinline__ void rfft_row(float* sm, const float* src, int L,
                                         int yloc, int lane, int warp) {
    float* fr = sm + FX_ROW + warp * 512;
    float* fi = fr + 256;
    for (int n = lane; n < 256; n += 32) {
        float xr = (2 * n < L)     ? src[2 * n]     : 0.f;
        float xi = (2 * n + 1 < L) ? src[2 * n + 1] : 0.f;
        int r = rev8(n);
        fr[r] = xr; fi[r] = xi;
    }
    __syncwarp();
    fft256(fr, fi, sm + FX_T256R, sm + FX_T256I, lane);
    // untangle: S[k] = Fe + w512[k]*Fo, k = 0..256
    float* tsr = sm + FX_TSR + yloc * NF;
    float* tsi = sm + FX_TSI + yloc * NF;
    for (int k = lane; k <= 256; k += 32) {
        const int k1 = k & 255, k2 = (256 - k) & 255;
        const float zr1 = fr[k1], zi1 = fi[k1];
        const float zr2 = fr[k2], zi2 = fi[k2];
        const float Fer = 0.5f * (zr1 + zr2);
        const float Fei = 0.5f * (zi1 - zi2);
        const float Dr  = zr1 - zr2;
        const float Di  = zi1 + zi2;
        const float For = 0.5f * Di;
        const float Foi = -0.5f * Dr;
        const float wr = sm[FX_T512R + k], wi = sm[FX_T512I + k];
        tsr[k] = Fer + wr * For - wi * Foi;
        tsi[k] = Fei + wr * Foi + wi * For;
    }
    __syncwarp();
}

// ---------------------------------------------------------------------------
// Signal forward FFT. CTA = (b, c, ytile of 32). Writes g_Sr/g_Si[b][f][c][y].
// ---------------------------------------------------------------------------
extern __shared__ float fx_sm[];

__global__ void __launch_bounds__(256) sig_fft(const float* __restrict__ sig) {
    const int tid = threadIdx.x, lane = tid & 31, warp = tid >> 5;
    const int ct = blockIdx.x;
    const int ytile = ct & 7, c = (ct >> 3) & 63, b = ct >> 9;
    load_tw(fx_sm, tid);
    __syncthreads();
    for (int batch = 0; batch < 4; batch++) {
        const int yloc = batch * 8 + warp;
        const int y = ytile * 32 + yloc;
        const float* src = sig + (((b * 64 + c) * 256 + y) << 8);
        rfft_row(fx_sm, src, 256, yloc, lane, warp);
    }
    __syncthreads();
    // write phase: [b][f][c][ytile*32 + yloc]
    for (int idx = tid; idx < NF * 32; idx += 256) {
        const int f = idx >> 5, yloc = idx & 31;
        const int dst = ((b * NF + f) * 64 + c) * 256 + ytile * 32 + yloc;
        g_Sr[dst] = fx_sm[FX_TSR + yloc * NF + f];
        g_Si[dst] = fx_sm[FX_TSI + yloc * NF + f];
    }
}

// ---------------------------------------------------------------------------
// Weight forward FFT + A-tile expansion. CTA = (ky, o, chalf of 32).
// Row (o, c, ky): w[o][c][ky][0..30] -> S[f]; writes g_wA[f][ky][o][c]=Wr,
// g_wA[f][ky][o][64+c]=Wi (tf32-rounded).
// ---------------------------------------------------------------------------
__global__ void __launch_bounds__(256) w_fft(const float* __restrict__ w) {
    const int tid = threadIdx.x, lane = tid & 31, warp = tid >> 5;
    const int ct = blockIdx.x;
    const int chalf = ct & 1, o = (ct >> 1) & 63, ky = ct >> 7;
    load_tw(fx_sm, tid);
    __syncthreads();
    for (int batch = 0; batch < 4; batch++) {
        const int yloc = batch * 8 + warp;      // c-local
        const int c = chalf * 32 + yloc;
        const float* src = w + ((o * 64 + c) * 31 + ky) * 31;
        rfft_row(fx_sm, src, 31, yloc, lane, warp);
    }
    __syncthreads();
    for (int idx = tid; idx < NF * 32; idx += 256) {
        const int f = idx >> 5, cl = idx & 31;
        const int c = chalf * 32 + cl;
        const float wr = __uint_as_float(f2tf(fx_sm[FX_TSR + cl * NF + f]));
        const float wi = __uint_as_float(f2tf(fx_sm[FX_TSI + cl * NF + f]));
        float* base = g_wA + (size_t)(f * KS + ky) * WA_ELEMS + o * WA_STRIDE;
        base[c]      = wr;
        base[64 + c] = wi;
    }
}

// ---------------------------------------------------------------------------
// Frequency-domain GEMM. Block = (b, f). Out_f[o,y] = sum_{c,ky} S*conj(W).
// sB[c2=128][y'(296)]: rows 0..63 = Sr[c][y'], 64..127 = Si[c][y'];
//   col j corresponds to y' = j-15 (zeros outside [0,255]).
// A-tiles [Wr|Wi] per (f,ky) cp.async double-buffered.
// Re += Ar*Br + Ai*Bi ; Im += Ar*Bi + Ai*(-Br).
// 8 warps = y-slices of 32; per warp mt=4 (o), nt=4, re/im -> 128 acc.
// ---------------------------------------------------------------------------
#define GX_SB 0
#define GX_WA (SB_ROWS * SB_STRIDE)                       // 37888 floats
#define GX_TOTAL (GX_WA + 2 * WA_ELEMS)                   // 54784 floats = 219136 B

__device__ __forceinline__ void mma_tf32(float* d, const unsigned* a,
                                         unsigned b0, unsigned b1) {
    asm volatile(
        "mma.sync.aligned.m16n8k8.row.col.f32.tf32.tf32.f32 "
        "{%0,%1,%2,%3}, {%4,%5,%6,%7}, {%8,%9}, {%0,%1,%2,%3};\n"
        : "+f"(d[0]), "+f"(d[1]), "+f"(d[2]), "+f"(d[3])
        : "r"(a[0]), "r"(a[1]), "r"(a[2]), "r"(a[3]), "r"(b0), "r"(b1));
}

__device__ __forceinline__ uint32_t s2u(const void* p) {
    uint32_t a;
    asm("{ .reg .u64 t; cvta.to.shared.u64 t, %1; cvt.u32.u64 %0, t; }" : "=r"(a) : "l"(p));
    return a;
}

extern __shared__ float gx_sm[];

__global__ void __launch_bounds__(256, 1) freq_gemm() {
    const int tid = threadIdx.x, lane = tid & 31, warp = tid >> 5;
    const int g = lane >> 2, t4 = lane & 3;
    const int b = blockIdx.x, f = blockIdx.y;

    float* sB = gx_sm + GX_SB;
    float* sW = gx_sm + GX_WA;
    const uint32_t swu = s2u(sW);

    float accRe[4][4][4], accIm[4][4][4];
#pragma unroll
    for (int mt = 0; mt < 4; mt++)
#pragma unroll
        for (int nt = 0; nt < 4; nt++)
#pragma unroll
            for (int r = 0; r < 4; r++) { accRe[mt][nt][r] = 0.f; accIm[mt][nt][r] = 0.f; }

    // issue A-tile(ky) -> slot ky&1 (33792 B = 2112 x 16B)
    auto issue_w = [&](int ky) {
        const float* src = g_wA + (size_t)(f * KS + ky) * WA_ELEMS;
        const uint32_t base = swu + (uint32_t)(ky & 1) * (WA_ELEMS * 4);
#pragma unroll
        for (int i = 0; i < 9; i++) {
            const int e = i * 256 + tid;
            if (e < WA_ELEMS / 4)
                asm volatile("cp.async.cg.shared.global [%0], [%1], 16;"
                             :: "r"(base + (uint32_t)e * 16u),
                                "l"((const float4*)src + e) : "memory");
        }
        asm volatile("cp.async.commit_group;" ::: "memory");
    };

    issue_w(0);

    // fill sB once: 128 rows, 16 rows per warp
    {
        const int rbase = warp * 16;
        for (int t = 0; t < 16; t++) {
            const int c2 = rbase + t;
            const float* src = (c2 < 64)
                ? g_Sr + (((b * NF + f) * 64 + c2) << 8)
                : g_Si + (((b * NF + f) * 64 + (c2 - 64)) << 8);
            float* dst = sB + c2 * SB_STRIDE;
            for (int j = lane; j < 286; j += 32) {
                float v = (j >= 15 && j < 271) ? src[j - 15] : 0.f;
                dst[j] = __uint_as_float(f2tf(v));
            }
        }
    }

    for (int ky = 0; ky < KS; ky++) {
        asm volatile("cp.async.wait_group 0;" ::: "memory");
        __syncthreads();                    // A(ky)+sB visible; MMA(ky-1) done
        if (ky + 1 < KS) issue_w(ky + 1);

        const float* wa = sW + (ky & 1) * WA_ELEMS;
#pragma unroll
        for (int cc = 0; cc < 8; cc++) {
            unsigned ar[4][4], ai[4][4];
#pragma unroll
            for (int mt = 0; mt < 4; mt++) {
                const float* p = wa + (mt * 16 + g) * WA_STRIDE + cc * 8 + t4;
                ar[mt][0] = __float_as_uint(p[0]);
                ar[mt][1] = __float_as_uint(p[8 * WA_STRIDE]);
                ar[mt][2] = __float_as_uint(p[4]);
                ar[mt][3] = __float_as_uint(p[8 * WA_STRIDE + 4]);
                ai[mt][0] = __float_as_uint(p[64]);
                ai[mt][1] = __float_as_uint(p[8 * WA_STRIDE + 64]);
                ai[mt][2] = __float_as_uint(p[68]);
                ai[mt][3] = __float_as_uint(p[8 * WA_STRIDE + 68]);
            }
            const int row = cc * 8 + t4;
            const int colb = warp * 32 + g + ky;
#pragma unroll
            for (int nt = 0; nt < 4; nt++) {
                const int col = colb + nt * 8;
                const unsigned br0 = __float_as_uint(sB[row * SB_STRIDE + col]);
                const unsigned br1 = __float_as_uint(sB[(row + 4) * SB_STRIDE + col]);
                const unsigned bi0 = __float_as_uint(sB[(row + 64) * SB_STRIDE + col]);
                const unsigned bi1 = __float_as_uint(sB[(row + 68) * SB_STRIDE + col]);
                const unsigned nbr0 = br0 ^ 0x80000000u;
                const unsigned nbr1 = br1 ^ 0x80000000u;
#pragma unroll
                for (int mt = 0; mt < 4; mt++) {
                    mma_tf32(accRe[mt][nt], ar[mt], br0, br1);
                    mma_tf32(accRe[mt][nt], ai[mt], bi0, bi1);
                    mma_tf32(accIm[mt][nt], ar[mt], bi0, bi1);
                    mma_tf32(accIm[mt][nt], ai[mt], nbr0, nbr1);
                }
            }
        }
    }

    // epilogue: g_Or/g_Oi[f][b][o][y]
#pragma unroll
    for (int mt = 0; mt < 4; mt++) {
#pragma unroll
        for (int r = 0; r < 2; r++) {
            const int o = mt * 16 + r * 8 + g;
            const int base = ((f * NBATCH + b) * COUT + o) << 8;
#pragma unroll
            for (int nt = 0; nt < 4; nt++) {
                const int y = warp * 32 + nt * 8 + t4 * 2;
                float2 vr, vi;
                vr.x = accRe[mt][nt][r * 2 + 0]; vr.y = accRe[mt][nt][r * 2 + 1];
                vi.x = accIm[mt][nt][r * 2 + 0]; vi.y = accIm[mt][nt][r * 2 + 1];
                *(float2*)(g_Or + base + y) = vr;
                *(float2*)(g_Oi + base + y) = vi;
            }
        }
    }
}

// ---------------------------------------------------------------------------
// Inverse rfft + shift + bias. CTA = (b, o, ytile of 32).
// Reads g_Or/g_Oi[f][b][o][y] -> ts[yloc][f]; per row: irfft-512;
// out[b][o][y][x] = r[(x-15) mod 512] + bias[o].
// ---------------------------------------------------------------------------
__global__ void __launch_bounds__(256) inv_fft(const float* __restrict__ bias,
                                               float* __restrict__ out) {
    const int tid = threadIdx.x, lane = tid & 31, warp = tid >> 5;
    const int ct = blockIdx.x;
    const int ytile = ct & 7, o = (ct >> 3) & 63, b = ct >> 9;
    const int y0 = ytile * 32;
    load_tw(fx_sm, tid);
    __syncthreads();
    // gather: ts[yloc][f] <- g_O*[f][b][o][y0+yloc]
    for (int idx = tid; idx < NF * 32; idx += 256) {
        const int f = idx >> 5, yloc = idx & 31;
        const int src = ((f * NBATCH + b) * COUT + o) * 256 + y0 + yloc;
        fx_sm[FX_TSR + yloc * NF + f] = g_Or[src];
        fx_sm[FX_TSI + yloc * NF + f] = g_Oi[src];
    }
    __syncthreads();
    const float bv = __ldg(bias + o);
    for (int batch = 0; batch < 4; batch++) {
        const int yloc = batch * 8 + warp;
        const int y = y0 + yloc;
        float* fr = fx_sm + FX_ROW + warp * 512;
        float* fi = fr + 256;
        const float* tsr = fx_sm + FX_TSR + yloc * NF;
        const float* tsi = fx_sm + FX_TSI + yloc * NF;
        // untangle inverse: Z[k] = Fe + i*Fo; store conj(Z) bit-reversed
        for (int k = lane; k < 256; k += 32) {
            const float Skr = tsr[k],      Ski = tsi[k];
            const float Smr = tsr[256 - k], Smi = tsi[256 - k];
            const float Fer = 0.5f * (Skr + Smr);
            const float Fei = 0.5f * (Ski - Smi);
            const float Dr = Skr - Smr;
            const float Di = Ski + Smi;
            const float wr = fx_sm[FX_T512R + k];
            const float wi = -fx_sm[FX_T512I + k];     // e^{+2pi i k/512}
            const float For = 0.5f * (wr * Dr - wi * Di);
            const float Foi = 0.5f * (wr * Di + wi * Dr);
            const float Zr = Fer - Foi;
            const float Zi = Fei + For;
            const int r = rev8(k);
            fr[r] = Zr; fi[r] = -Zi;                   // conj(Z)
        }
        __syncwarp();
        fft256(fr, fi, fx_sm + FX_T256R, fx_sm + FX_T256I, lane);
        // z[n] = conj(F)/256 ; x[2n]=Re z, x[2n+1]=Im z = -fi/256
        float* orow = out + (((b * COUT + o) * 256 + y) << 8);
        const float inv = 1.0f / 256.0f;
        for (int x = lane; x < 256; x += 32) {
            const int n2 = (x + 497) & 511;            // (x - 15) mod 512
            const int h = n2 >> 1;
            const float v = (n2 & 1) ? (-fi[h]) : fr[h];
            orow[x] = v * inv + bv;
        }
        __syncwarp();
    }
}

// ---------------------------------------------------------------------------
extern "C" void kernel_launch(void* const* d_in, const int* in_sizes, int n_in,
                              void* d_out, int out_size) {
    const float* sig  = (const float*)d_in[0];
    const float* w    = (const float*)d_in[1];
    const float* bias = (const float*)d_in[2];
    float* out        = (float*)d_out;

    const size_t fx_bytes = (size_t)FX_TOTAL * sizeof(float);   // 85,256
    const size_t gx_bytes = (size_t)GX_TOTAL * sizeof(float);   // 219,136
    cudaFuncSetAttribute(sig_fft,  cudaFuncAttributeMaxDynamicSharedMemorySize, (int)fx_bytes);
    cudaFuncSetAttribute(w_fft,    cudaFuncAttributeMaxDynamicSharedMemorySize, (int)fx_bytes);
    cudaFuncSetAttribute(inv_fft,  cudaFuncAttributeMaxDynamicSharedMemorySize, (int)fx_bytes);
    cudaFuncSetAttribute(freq_gemm, cudaFuncAttributeMaxDynamicSharedMemorySize, (int)gx_bytes);

    tw_init<<<1, 512>>>();
    sig_fft<<<NBATCH * CIN * 8, 256, fx_bytes>>>(sig);          // 4096 CTAs
    w_fft<<<KS * COUT * 2, 256, fx_bytes>>>(w);                 // 3968 CTAs
    freq_gemm<<<dim3(NBATCH, NF), 256, gx_bytes>>>();           // 8 x 257
    inv_fft<<<NBATCH * COUT * 8, 256, fx_bytes>>>(bias, out);   // 4096 CTAs
}

// round 15
// speedup vs baseline: 7.2668x; 1.3884x over previous
#include <cuda_runtime.h>
#include <cuda_fp16.h>
#include <cstdint>

// Problem constants
#define SIG_HW 256
#define CIN    64
#define COUT   64
#define KS     31
#define PADK   15
#define NBATCH 8
#define NF     257           // rfft-512 bins

// GEMM smem geometry (uint32 units)
#define SB_STRIDE 296        // uint32 per c-pair row; 296%32==8 -> conflict-free
#define SB_ROWS   64         // 32 Sr-pair rows + 32 Si-pair rows
#define WA_STRIDE 68         // uint32 per o-row: 32 Ar-pairs | 32 Ai-pairs | 4 pad
#define WA_ELEMS  (COUT * WA_STRIDE)             // 4352 u32 per (f,ky) A-tile (smem)
#define WA_GELEMS (COUT * 64)                    // 4096 u32 per tile in global (no pad)
#define GX_WA     (SB_ROWS * SB_STRIDE)          // 18944
#define GX_TOTAL  (GX_WA + 2 * WA_ELEMS)         // 27648 u32 = 110592 B

// -------- device scratch --------
__device__ __half g_Sr[NBATCH * NF * CIN * 256];   // [b][f][c][y]
__device__ __half g_Si[NBATCH * NF * CIN * 256];
__device__ unsigned g_wA[NF * KS * WA_GELEMS];     // [f][ky][o][64 u32] = ArP|AiP
__device__ float g_Or[NF * NBATCH * COUT * 256];   // [f][b][o][y]
__device__ float g_Oi[NF * NBATCH * COUT * 256];
__device__ float g_t256r[128], g_t256i[128];
__device__ float g_t512r[NF],  g_t512i[NF];

__device__ __forceinline__ int rev8(int n) { return (int)(__brev((unsigned)n) >> 24); }

__global__ void tw_init() {
    int k = threadIdx.x;
    if (k < 128) {
        float s, c;
        sincospif((float)k / 128.0f, &s, &c);
        g_t256r[k] = c; g_t256i[k] = -s;
    }
    if (k < NF) {
        float s, c;
        sincospif((float)k / 256.0f, &s, &c);
        g_t512r[k] = c; g_t512i[k] = -s;
    }
}

// ---------------------------------------------------------------------------
// In-smem 256-pt complex FFT, one warp, DIT radix-2, bit-reversed input order.
// ---------------------------------------------------------------------------
__device__ __forceinline__ void fft256(float* fr, float* fi,
                                       const float* twr, const float* twi,
                                       int lane) {
    for (int len = 2; len <= 256; len <<= 1) {
        const int half = len >> 1;
        const int step = 256 / len;
        for (int j = lane; j < 128; j += 32) {
            const int pos  = j & (half - 1);
            const int idx0 = ((j & ~(half - 1)) << 1) + pos;
            const int idx1 = idx0 + half;
            const float wr = twr[pos * step], wi = twi[pos * step];
            const float ar1 = fr[idx1], ai1 = fi[idx1];
            const float tr = wr * ar1 - wi * ai1;
            const float ti = wr * ai1 + wi * ar1;
            const float ar0 = fr[idx0], ai0 = fi[idx0];
            fr[idx1] = ar0 - tr;  fi[idx1] = ai0 - ti;
            fr[idx0] = ar0 + tr;  fi[idx0] = ai0 + ti;
        }
        __syncwarp();
    }
}

#define FX_T256R 0
#define FX_T256I 128
#define FX_T512R 256
#define FX_T512I 513
#define FX_ROW   770
#define FX_TSR   (FX_ROW + 8 * 512)
#define FX_TSI   (FX_TSR + 32 * NF)
#define FX_TOTAL (FX_TSI + 32 * NF)          // 21314 floats = 85256 B

__device__ __forceinline__ void load_tw(float* sm, int tid) {
    for (int i = tid; i < 128; i += 256) { sm[FX_T256R + i] = g_t256r[i]; sm[FX_T256I + i] = g_t256i[i]; }
    for (int i = tid; i < NF;  i += 256) { sm[FX_T512R + i] = g_t512r[i]; sm[FX_T512I + i] = g_t512i[i]; }
}

// rfft-512 of a real row (first L samples, rest zero) -> ts[yloc][0..256]
__device__ __forceinline__ void rfft_row(float* sm, const float* src, int L,
                                         int yloc, int lane, int warp) {
    float* fr = sm + FX_ROW + warp * 512;
    float* fi = fr + 256;
    for (int n = lane; n < 256; n += 32) {
        float xr = (2 * n < L)     ? src[2 * n]     : 0.f;
        float xi = (2 * n + 1 < L) ? src[2 * n + 1] : 0.f;
        int r = rev8(n);
        fr[r] = xr; fi[r] = xi;
    }
    __syncwarp();
    fft256(fr, fi, sm + FX_T256R, sm + FX_T256I, lane);
    float* tsr = sm + FX_TSR + yloc * NF;
    float* tsi = sm + FX_TSI + yloc * NF;
    for (int k = lane; k <= 256; k += 32) {
        const int k1 = k & 255, k2 = (256 - k) & 255;
        const float zr1 = fr[k1], zi1 = fi[k1];
        const float zr2 = fr[k2], zi2 = fi[k2];
        const float Fer = 0.5f * (zr1 + zr2);
        const float Fei = 0.5f * (zi1 - zi2);
        const float Dr  = zr1 - zr2;
        const float Di  = zi1 + zi2;
        const float For = 0.5f * Di;
        const float Foi = -0.5f * Dr;
        const float wr = sm[FX_T512R + k], wi = sm[FX_T512I + k];
        tsr[k] = Fer + wr * For - wi * Foi;
        tsi[k] = Fei + wr * Foi + wi * For;
    }
    __syncwarp();
}

extern __shared__ float fx_sm[];

// ---------------------------------------------------------------------------
// Merged forward FFT: blocks [0, 4096) = signal, [4096, 8064) = weights.
// Signal: CTA = (b, c, ytile of 32) -> g_Sr/g_Si[b][f][c][y] (fp16).
// Weight: CTA = (ky, o, chalf of 32) -> g_wA[f][ky][o][ArP|AiP] (fp16 pairs).
// ---------------------------------------------------------------------------
__global__ void __launch_bounds__(256) fwd_fft(const float* __restrict__ sig,
                                               const float* __restrict__ w) {
    const int tid = threadIdx.x, lane = tid & 31, warp = tid >> 5;
    load_tw(fx_sm, tid);
    __syncthreads();

    if (blockIdx.x < 4096) {
        const int ct = blockIdx.x;
        const int ytile = ct & 7, c = (ct >> 3) & 63, b = ct >> 9;
        for (int batch = 0; batch < 4; batch++) {
            const int yloc = batch * 8 + warp;
            const int y = ytile * 32 + yloc;
            const float* src = sig + (((b * 64 + c) * 256 + y) << 8);
            rfft_row(fx_sm, src, 256, yloc, lane, warp);
        }
        __syncthreads();
        for (int idx = tid; idx < NF * 32; idx += 256) {
            const int f = idx >> 5, yloc = idx & 31;
            const int dst = ((b * NF + f) * 64 + c) * 256 + ytile * 32 + yloc;
            g_Sr[dst] = __float2half_rn(fx_sm[FX_TSR + yloc * NF + f]);
            g_Si[dst] = __float2half_rn(fx_sm[FX_TSI + yloc * NF + f]);
        }
    } else {
        const int ct = blockIdx.x - 4096;
        const int chalf = ct & 1, o = (ct >> 1) & 63, ky = ct >> 7;
        for (int batch = 0; batch < 4; batch++) {
            const int cl = batch * 8 + warp;
            const int c = chalf * 32 + cl;
            const float* src = w + ((o * 64 + c) * 31 + ky) * 31;
            rfft_row(fx_sm, src, 31, cl, lane, warp);
        }
        __syncthreads();
        for (int idx = tid; idx < NF * 32; idx += 256) {
            const int f = idx >> 5, cl = idx & 31;
            const int c = chalf * 32 + cl;
            __half* base = (__half*)g_wA
                + (((size_t)(f * KS + ky) * COUT + o) << 7);   // *128 halves
            base[c]      = __float2half_rn(fx_sm[FX_TSR + cl * NF + f]);
            base[64 + c] = __float2half_rn(fx_sm[FX_TSI + cl * NF + f]);
        }
    }
}

// ---------------------------------------------------------------------------
// Frequency-domain GEMM (fp16 operands, fp32 accum). Block = (b, f).
// sB: 64 u32 rows; rows 0..31 = Sr c-pairs, 32..63 = Si c-pairs; col j = y'=j-15.
// A-tiles per (f,ky): [o][ArP(32)|AiP(32)] u32, stride 68, cp.async dbl-buffered.
// Re += Ar*Br + Ai*Bi ; Im += Ar*Bi - Ai*Br (conj via sign-XOR of packed halves).
// 8 warps = y-slices of 32; per warp mt=4 (o), nt=4, re/im -> 128 acc.
// ---------------------------------------------------------------------------
__device__ __forceinline__ void mma_f16(float* d, const unsigned* a,
                                        unsigned b0, unsigned b1) {
    asm volatile(
        "mma.sync.aligned.m16n8k16.row.col.f32.f16.f16.f32 "
        "{%0,%1,%2,%3}, {%4,%5,%6,%7}, {%8,%9}, {%0,%1,%2,%3};\n"
        : "+f"(d[0]), "+f"(d[1]), "+f"(d[2]), "+f"(d[3])
        : "r"(a[0]), "r"(a[1]), "r"(a[2]), "r"(a[3]), "r"(b0), "r"(b1));
}

__device__ __forceinline__ uint32_t s2u(const void* p) {
    uint32_t a;
    asm("{ .reg .u64 t; cvta.to.shared.u64 t, %1; cvt.u32.u64 %0, t; }" : "=r"(a) : "l"(p));
    return a;
}

extern __shared__ unsigned gx_sm[];

__global__ void __launch_bounds__(256, 1) freq_gemm() {
    const int tid = threadIdx.x, lane = tid & 31, warp = tid >> 5;
    const int g = lane >> 2, t4 = lane & 3;
    const int b = blockIdx.x, f = blockIdx.y;

    unsigned* sB = gx_sm;
    unsigned* sW = gx_sm + GX_WA;
    const uint32_t swu = s2u(sW);

    float accRe[4][4][4], accIm[4][4][4];
#pragma unroll
    for (int mt = 0; mt < 4; mt++)
#pragma unroll
        for (int nt = 0; nt < 4; nt++)
#pragma unroll
            for (int r = 0; r < 4; r++) { accRe[mt][nt][r] = 0.f; accIm[mt][nt][r] = 0.f; }

    // issue A-tile(ky) -> slot ky&1 (16384 B global -> 17408 B padded smem)
    auto issue_w = [&](int ky) {
        const float4* src = (const float4*)(g_wA + (size_t)(f * KS + ky) * WA_GELEMS);
        const uint32_t base = swu + (uint32_t)(ky & 1) * (WA_ELEMS * 4);
#pragma unroll
        for (int i = 0; i < 4; i++) {
            const int e = i * 256 + tid;            // 0..1023 chunks of 16B
            const int row = e >> 4, c16 = e & 15;
            asm volatile("cp.async.cg.shared.global [%0], [%1], 16;"
                         :: "r"(base + (uint32_t)(row * WA_STRIDE + c16 * 4) * 4u),
                            "l"(src + e) : "memory");
        }
        asm volatile("cp.async.commit_group;" ::: "memory");
    };

    issue_w(0);

    // fill sB: 128 half-rows (Sr c / Si c), pair-packed (lo = even c)
    {
        const int rbase = warp * 16;
        __half* sBh = (__half*)sB;
        for (int t = 0; t < 16; t++) {
            const int c2 = rbase + t;
            const int c = c2 & 63;
            const __half* src = (c2 < 64)
                ? g_Sr + (((b * NF + f) * 64 + c) << 8)
                : g_Si + (((b * NF + f) * 64 + c) << 8);
            __half* dst = sBh + ((size_t)((c >> 1) + (c2 < 64 ? 0 : 32)) * SB_STRIDE) * 2
                        + (c & 1);
            for (int j = lane; j < 286; j += 32) {
                __half v = (j >= 15 && j < 271) ? src[j - 15] : __float2half_rn(0.f);
                dst[j * 2] = v;
            }
        }
    }

    for (int ky = 0; ky < KS; ky++) {
        asm volatile("cp.async.wait_group 0;" ::: "memory");
        __syncthreads();                    // A(ky)+sB visible; MMA(ky-1) done
        if (ky + 1 < KS) issue_w(ky + 1);

        const unsigned* wa = sW + (ky & 1) * WA_ELEMS;
#pragma unroll
        for (int cc = 0; cc < 4; cc++) {    // K=16 chunks over c=64
            const int p0 = cc * 8 + t4;
            unsigned ar[4][4], ai[4][4];
#pragma unroll
            for (int mt = 0; mt < 4; mt++) {
                const unsigned* pw = wa + (mt * 16 + g) * WA_STRIDE;
                ar[mt][0] = pw[p0];
                ar[mt][1] = pw[8 * WA_STRIDE + p0];
                ar[mt][2] = pw[p0 + 4];
                ar[mt][3] = pw[8 * WA_STRIDE + p0 + 4];
                ai[mt][0] = pw[32 + p0];
                ai[mt][1] = pw[8 * WA_STRIDE + 32 + p0];
                ai[mt][2] = pw[32 + p0 + 4];
                ai[mt][3] = pw[8 * WA_STRIDE + 32 + p0 + 4];
            }
            const int colb = warp * 32 + g + ky;
#pragma unroll
            for (int nt = 0; nt < 4; nt++) {
                const int col = colb + nt * 8;
                const unsigned br0 = sB[p0 * SB_STRIDE + col];
                const unsigned br1 = sB[(p0 + 4) * SB_STRIDE + col];
                const unsigned bi0 = sB[(32 + p0) * SB_STRIDE + col];
                const unsigned bi1 = sB[(32 + p0 + 4) * SB_STRIDE + col];
                const unsigned nbr0 = br0 ^ 0x80008000u;
                const unsigned nbr1 = br1 ^ 0x80008000u;
#pragma unroll
                for (int mt = 0; mt < 4; mt++) {
                    mma_f16(accRe[mt][nt], ar[mt], br0, br1);
                    mma_f16(accRe[mt][nt], ai[mt], bi0, bi1);
                    mma_f16(accIm[mt][nt], ar[mt], bi0, bi1);
                    mma_f16(accIm[mt][nt], ai[mt], nbr0, nbr1);
                }
            }
        }
    }

    // epilogue: g_Or/g_Oi[f][b][o][y]
#pragma unroll
    for (int mt = 0; mt < 4; mt++) {
#pragma unroll
        for (int r = 0; r < 2; r++) {
            const int o = mt * 16 + r * 8 + g;
            const int base = ((f * NBATCH + b) * COUT + o) << 8;
#pragma unroll
            for (int nt = 0; nt < 4; nt++) {
                const int y = warp * 32 + nt * 8 + t4 * 2;
                float2 vr, vi;
                vr.x = accRe[mt][nt][r * 2 + 0]; vr.y = accRe[mt][nt][r * 2 + 1];
                vi.x = accIm[mt][nt][r * 2 + 0]; vi.y = accIm[mt][nt][r * 2 + 1];
                *(float2*)(g_Or + base + y) = vr;
                *(float2*)(g_Oi + base + y) = vi;
            }
        }
    }
}

// ---------------------------------------------------------------------------
// Inverse rfft + shift + bias. CTA = (b, o, ytile of 32).
// ---------------------------------------------------------------------------
__global__ void __launch_bounds__(256) inv_fft(const float* __restrict__ bias,
                                               float* __restrict__ out) {
    const int tid = threadIdx.x, lane = tid & 31, warp = tid >> 5;
    const int ct = blockIdx.x;
    const int ytile = ct & 7, o = (ct >> 3) & 63, b = ct >> 9;
    const int y0 = ytile * 32;
    load_tw(fx_sm, tid);
    __syncthreads();
    for (int idx = tid; idx < NF * 32; idx += 256) {
        const int f = idx >> 5, yloc = idx & 31;
        const int src = ((f * NBATCH + b) * COUT + o) * 256 + y0 + yloc;
        fx_sm[FX_TSR + yloc * NF + f] = g_Or[src];
        fx_sm[FX_TSI + yloc * NF + f] = g_Oi[src];
    }
    __syncthreads();
    const float bv = __ldg(bias + o);
    for (int batch = 0; batch < 4; batch++) {
        const int yloc = batch * 8 + warp;
        const int y = y0 + yloc;
        float* fr = fx_sm + FX_ROW + warp * 512;
        float* fi = fr + 256;
        const float* tsr = fx_sm + FX_TSR + yloc * NF;
        const float* tsi = fx_sm + FX_TSI + yloc * NF;
        for (int k = lane; k < 256; k += 32) {
            const float Skr = tsr[k],      Ski = tsi[k];
            const float Smr = tsr[256 - k], Smi = tsi[256 - k];
            const float Fer = 0.5f * (Skr + Smr);
            const float Fei = 0.5f * (Ski - Smi);
            const float Dr = Skr - Smr;
            const float Di = Ski + Smi;
            const float wr = fx_sm[FX_T512R + k];
            const float wi = -fx_sm[FX_T512I + k];
            const float For = 0.5f * (wr * Dr - wi * Di);
            const float Foi = 0.5f * (wr * Di + wi * Dr);
            const float Zr = Fer - Foi;
            const float Zi = Fei + For;
            const int r = rev8(k);
            fr[r] = Zr; fi[r] = -Zi;
        }
        __syncwarp();
        fft256(fr, fi, fx_sm + FX_T256R, fx_sm + FX_T256I, lane);
        float* orow = out + (((b * COUT + o) * 256 + y) << 8);
        const float inv = 1.0f / 256.0f;
        for (int x = lane; x < 256; x += 32) {
            const int n2 = (x + 497) & 511;            // (x - 15) mod 512
            const int h = n2 >> 1;
            const float v = (n2 & 1) ? (-fi[h]) : fr[h];
            orow[x] = v * inv + bv;
        }
        __syncwarp();
    }
}

// ---------------------------------------------------------------------------
extern "C" void kernel_launch(void* const* d_in, const int* in_sizes, int n_in,
                              void* d_out, int out_size) {
    const float* sig  = (const float*)d_in[0];
    const float* w    = (const float*)d_in[1];
    const float* bias = (const float*)d_in[2];
    float* out        = (float*)d_out;

    const size_t fx_bytes = (size_t)FX_TOTAL * sizeof(float);     // 85,256
    const size_t gx_bytes = (size_t)GX_TOTAL * sizeof(unsigned);  // 110,592
    cudaFuncSetAttribute(fwd_fft,  cudaFuncAttributeMaxDynamicSharedMemorySize, (int)fx_bytes);
    cudaFuncSetAttribute(inv_fft,  cudaFuncAttributeMaxDynamicSharedMemorySize, (int)fx_bytes);
    cudaFuncSetAttribute(freq_gemm, cudaFuncAttributeMaxDynamicSharedMemorySize, (int)gx_bytes);

    tw_init<<<1, 512>>>();
    fwd_fft<<<4096 + KS * COUT * 2, 256, fx_bytes>>>(sig, w);   // 8064 CTAs
    freq_gemm<<<dim3(NBATCH, NF), 256, gx_bytes>>>();           // 8 x 257
    inv_fft<<<NBATCH * COUT * 8, 256, fx_bytes>>>(bias, out);   // 4096 CTAs
}

// round 16
// speedup vs baseline: 8.2130x; 1.1302x over previous
#include <cuda_runtime.h>
#include <cuda_fp16.h>
#include <cstdint>

// Problem constants
#define SIG_HW 256
#define CIN    64
#define COUT   64
#define KS     31
#define PADK   15
#define NBATCH 8
#define NF     257           // rfft-512 bins

// GEMM smem geometry (uint32 units)
#define SB_STRIDE 296        // uint32 per c-pair row; 296%32==8 -> conflict-free
#define SB_ROWS   64         // 32 Sr-pair rows + 32 Si-pair rows
#define WA_STRIDE 68         // uint32 per o-row: 32 Ar-pairs | 32 Ai-pairs | 4 pad
#define WA_ELEMS  (COUT * WA_STRIDE)             // 4352 u32 per (f,ky) A-tile (smem)
#define WA_GELEMS (COUT * 64)                    // 4096 u32 per tile in global (no pad)
#define GX_WA     (SB_ROWS * SB_STRIDE)          // 18944
#define GX_TOTAL  (GX_WA + 2 * WA_ELEMS)         // 27648 u32 = 110592 B

// -------- device scratch --------
__device__ __half g_Sr[NBATCH * NF * CIN * 256];   // [b][f][c][y]
__device__ __half g_Si[NBATCH * NF * CIN * 256];
__device__ unsigned g_wA[NF * KS * WA_GELEMS];     // [f][ky][o][64 u32] = ArP|AiP
__device__ float g_Or[NF * NBATCH * COUT * 256];   // [f][b][o][y]
__device__ float g_Oi[NF * NBATCH * COUT * 256];
__device__ float g_t256r[256], g_t256i[256];       // e^{-2pi i k/256}, k=0..255
__device__ float g_t512r[NF],  g_t512i[NF];        // e^{-2pi i k/512}

// base-4 digit reversal of 8-bit index
__device__ __forceinline__ int rev4(int n) {
    return ((n & 3) << 6) | ((n & 12) << 2) | ((n >> 2) & 12) | ((n >> 6) & 3);
}

__global__ void tw_init() {
    int k = threadIdx.x;
    if (k < 256) {
        float s, c;
        sincospif((float)k / 128.0f, &s, &c);
        g_t256r[k] = c; g_t256i[k] = -s;
    }
    if (k < NF) {
        float s, c;
        sincospif((float)k / 256.0f, &s, &c);
        g_t512r[k] = c; g_t512i[k] = -s;
    }
}

// ---------------------------------------------------------------------------
// In-smem 256-pt complex FFT, one warp, DIT RADIX-4 (4 stages), input in
// base-4 digit-reversed order. twr/twi: 256-entry e^{-2pi i k/256} table.
// ---------------------------------------------------------------------------
__device__ __forceinline__ void fft256_r4(float* fr, float* fi,
                                          const float* twr, const float* twi,
                                          int lane) {
#pragma unroll
    for (int s = 0; s < 4; s++) {
        const int qsh     = 2 * s;           // log2(quarter)
        const int quarter = 1 << qsh;
        const int step    = 64 >> qsh;       // 256 / len, len = 4*quarter
#pragma unroll
        for (int mm = 0; mm < 2; mm++) {
            const int m  = mm * 32 + lane;   // butterfly id 0..63
            const int j  = m & (quarter - 1);
            const int i0 = ((m >> qsh) << (qsh + 2)) + j;   // g*len + j
            const int i1 = i0 + quarter;
            const int i2 = i1 + quarter;
            const int i3 = i2 + quarter;
            const int tj = j * step;
            const float w1r = twr[tj],      w1i = twi[tj];
            const float w2r = twr[2 * tj],  w2i = twi[2 * tj];
            const float w3r = twr[3 * tj],  w3i = twi[3 * tj];
            const float x0r = fr[i0], x0i = fi[i0];
            const float x1r = fr[i1], x1i = fi[i1];
            const float x2r = fr[i2], x2i = fi[i2];
            const float x3r = fr[i3], x3i = fi[i3];
            const float b1r = w1r * x1r - w1i * x1i, b1i = w1r * x1i + w1i * x1r;
            const float b2r = w2r * x2r - w2i * x2i, b2i = w2r * x2i + w2i * x2r;
            const float b3r = w3r * x3r - w3i * x3i, b3i = w3r * x3i + w3i * x3r;
            const float p0r = x0r + b2r, p0i = x0i + b2i;
            const float m0r = x0r - b2r, m0i = x0i - b2i;
            const float p1r = b1r + b3r, p1i = b1i + b3i;
            const float m1r = b1r - b3r, m1i = b1i - b3i;
            fr[i0] = p0r + p1r;  fi[i0] = p0i + p1i;
            fr[i2] = p0r - p1r;  fi[i2] = p0i - p1i;
            fr[i1] = m0r + m1i;  fi[i1] = m0i - m1r;   // (x0-b2) - i(b1-b3)
            fr[i3] = m0r - m1i;  fi[i3] = m0i + m1r;   // (x0-b2) + i(b1-b3)
        }
        __syncwarp();
    }
}

// smem layout for FFT kernels (floats)
#define FX_T256R 0
#define FX_T256I 256
#define FX_T512R 512
#define FX_T512I (512 + 257)
#define FX_ROW   1026
#define FX_TSR   (FX_ROW + 8 * 512)          // 5122
#define FX_TSI   (FX_TSR + 32 * NF)
#define FX_TOTAL (FX_TSI + 32 * NF)          // 21570 floats = 86280 B

__device__ __forceinline__ void load_tw(float* sm, int tid) {
    for (int i = tid; i < 256; i += 256) { sm[FX_T256R + i] = g_t256r[i]; sm[FX_T256I + i] = g_t256i[i]; }
    for (int i = tid; i < NF;  i += 256) { sm[FX_T512R + i] = g_t512r[i]; sm[FX_T512I + i] = g_t512i[i]; }
}

// rfft-512 of a real row (first L samples, rest zero) -> ts[yloc][0..256]
__device__ __forceinline__ void rfft_row(float* sm, const float* src, int L,
                                         int yloc, int lane, int warp) {
    float* fr = sm + FX_ROW + warp * 512;
    float* fi = fr + 256;
    for (int n = lane; n < 256; n += 32) {
        float xr = (2 * n < L)     ? src[2 * n]     : 0.f;
        float xi = (2 * n + 1 < L) ? src[2 * n + 1] : 0.f;
        int r = rev4(n);
        fr[r] = xr; fi[r] = xi;
    }
    __syncwarp();
    fft256_r4(fr, fi, sm + FX_T256R, sm + FX_T256I, lane);
    float* tsr = sm + FX_TSR + yloc * NF;
    float* tsi = sm + FX_TSI + yloc * NF;
    for (int k = lane; k <= 256; k += 32) {
        const int k1 = k & 255, k2 = (256 - k) & 255;
        const float zr1 = fr[k1], zi1 = fi[k1];
        const float zr2 = fr[k2], zi2 = fi[k2];
        const float Fer = 0.5f * (zr1 + zr2);
        const float Fei = 0.5f * (zi1 - zi2);
        const float Dr  = zr1 - zr2;
        const float Di  = zi1 + zi2;
        const float For = 0.5f * Di;
        const float Foi = -0.5f * Dr;
        const float wr = sm[FX_T512R + k], wi = sm[FX_T512I + k];
        tsr[k] = Fer + wr * For - wi * Foi;
        tsi[k] = Fei + wr * Foi + wi * For;
    }
    __syncwarp();
}

extern __shared__ float fx_sm[];

// ---------------------------------------------------------------------------
// Merged forward transform.
// Blocks [0,4096): signal rfft. CTA = (b, c, ytile of 32) -> g_Sr/g_Si (fp16).
// Blocks [4096,6080): weight DIRECT DFT. CTA = (ky, o): 31-tap table DFT,
//   W[f] = sum_kx w*e^{-2pi i f kx/512} -> g_wA[f][ky][o][ArP|AiP] fp16 pairs.
// ---------------------------------------------------------------------------
__global__ void __launch_bounds__(256) fwd_fft(const float* __restrict__ sig,
                                               const float* __restrict__ w) {
    const int tid = threadIdx.x, lane = tid & 31, warp = tid >> 5;

    if (blockIdx.x < 4096) {
        load_tw(fx_sm, tid);
        __syncthreads();
        const int ct = blockIdx.x;
        const int ytile = ct & 7, c = (ct >> 3) & 63, b = ct >> 9;
        for (int batch = 0; batch < 4; batch++) {
            const int yloc = batch * 8 + warp;
            const int y = ytile * 32 + yloc;
            const float* src = sig + (((b * 64 + c) * 256 + y) << 8);
            rfft_row(fx_sm, src, 256, yloc, lane, warp);
        }
        __syncthreads();
        for (int idx = tid; idx < NF * 32; idx += 256) {
            const int f = idx >> 5, yloc = idx & 31;
            const int dst = ((b * NF + f) * 64 + c) * 256 + ytile * 32 + yloc;
            g_Sr[dst] = __float2half_rn(fx_sm[FX_TSR + yloc * NF + f]);
            g_Si[dst] = __float2half_rn(fx_sm[FX_TSI + yloc * NF + f]);
        }
    } else {
        // -------- weight direct DFT --------
        const int ct = (int)blockIdx.x - 4096;    // 0..1983
        const int o  = ct & 63, ky = ct >> 6;
        float* sw   = fx_sm;                      // [64][31] w values
        float* ctab = fx_sm + 64 * 31;            // [512] cos
        float* stab = ctab + 512;                 // [512] sin
        for (int i = tid; i < 64 * 31; i += 256) {
            const int c = i / 31, kx = i - c * 31;
            sw[i] = w[((o * 64 + c) * 31 + ky) * 31 + kx];
        }
        for (int k = tid; k < 512; k += 256) {
            float s, cc;
            sincospif((float)k / 256.0f, &s, &cc);
            ctab[k] = cc; stab[k] = s;
        }
        __syncthreads();
        const int c  = tid & 63;
        const int fg = tid >> 6;                  // 0..3
        float wv[31];
#pragma unroll
        for (int kx = 0; kx < 31; kx++) wv[kx] = sw[c * 31 + kx];
        for (int f = fg; f < NF; f += 4) {
            float ar = 0.f, ai = 0.f;
#pragma unroll
            for (int kx = 0; kx < 31; kx++) {
                const int idx = (f * kx) & 511;
                ar = fmaf(wv[kx], ctab[idx], ar);
                ai = fmaf(wv[kx], stab[idx], ai);
            }
            __half* base = (__half*)g_wA + (((size_t)(f * KS + ky) * COUT + o) << 7);
            base[c]      = __float2half_rn(ar);
            base[64 + c] = __float2half_rn(-ai);   // W = FFT: Wi = -sum w*sin
        }
    }
}

// ---------------------------------------------------------------------------
// Frequency-domain GEMM (fp16 operands, fp32 accum). Block = (b, f).
// ---------------------------------------------------------------------------
__device__ __forceinline__ void mma_f16(float* d, const unsigned* a,
                                        unsigned b0, unsigned b1) {
    asm volatile(
        "mma.sync.aligned.m16n8k16.row.col.f32.f16.f16.f32 "
        "{%0,%1,%2,%3}, {%4,%5,%6,%7}, {%8,%9}, {%0,%1,%2,%3};\n"
        : "+f"(d[0]), "+f"(d[1]), "+f"(d[2]), "+f"(d[3])
        : "r"(a[0]), "r"(a[1]), "r"(a[2]), "r"(a[3]), "r"(b0), "r"(b1));
}

__device__ __forceinline__ uint32_t s2u(const void* p) {
    uint32_t a;
    asm("{ .reg .u64 t; cvta.to.shared.u64 t, %1; cvt.u32.u64 %0, t; }" : "=r"(a) : "l"(p));
    return a;
}

extern __shared__ unsigned gx_sm[];

__global__ void __launch_bounds__(256, 1) freq_gemm() {
    const int tid = threadIdx.x, lane = tid & 31, warp = tid >> 5;
    const int g = lane >> 2, t4 = lane & 3;
    const int b = blockIdx.x, f = blockIdx.y;

    unsigned* sB = gx_sm;
    unsigned* sW = gx_sm + GX_WA;
    const uint32_t swu = s2u(sW);

    float accRe[4][4][4], accIm[4][4][4];
#pragma unroll
    for (int mt = 0; mt < 4; mt++)
#pragma unroll
        for (int nt = 0; nt < 4; nt++)
#pragma unroll
            for (int r = 0; r < 4; r++) { accRe[mt][nt][r] = 0.f; accIm[mt][nt][r] = 0.f; }

    auto issue_w = [&](int ky) {
        const float4* src = (const float4*)(g_wA + (size_t)(f * KS + ky) * WA_GELEMS);
        const uint32_t base = swu + (uint32_t)(ky & 1) * (WA_ELEMS * 4);
#pragma unroll
        for (int i = 0; i < 4; i++) {
            const int e = i * 256 + tid;
            const int row = e >> 4, c16 = e & 15;
            asm volatile("cp.async.cg.shared.global [%0], [%1], 16;"
                         :: "r"(base + (uint32_t)(row * WA_STRIDE + c16 * 4) * 4u),
                            "l"(src + e) : "memory");
        }
        asm volatile("cp.async.commit_group;" ::: "memory");
    };

    issue_w(0);

    // fill sB: 128 half-rows (Sr c / Si c), pair-packed (lo = even c)
    {
        const int rbase = warp * 16;
        __half* sBh = (__half*)sB;
        for (int t = 0; t < 16; t++) {
            const int c2 = rbase + t;
            const int c = c2 & 63;
            const __half* src = (c2 < 64)
                ? g_Sr + (((b * NF + f) * 64 + c) << 8)
                : g_Si + (((b * NF + f) * 64 + c) << 8);
            __half* dst = sBh + ((size_t)((c >> 1) + (c2 < 64 ? 0 : 32)) * SB_STRIDE) * 2
                        + (c & 1);
            for (int j = lane; j < 286; j += 32) {
                __half v = (j >= 15 && j < 271) ? src[j - 15] : __float2half_rn(0.f);
                dst[j * 2] = v;
            }
        }
    }

    for (int ky = 0; ky < KS; ky++) {
        asm volatile("cp.async.wait_group 0;" ::: "memory");
        __syncthreads();
        if (ky + 1 < KS) issue_w(ky + 1);

        const unsigned* wa = sW + (ky & 1) * WA_ELEMS;
#pragma unroll
        for (int cc = 0; cc < 4; cc++) {
            const int p0 = cc * 8 + t4;
            unsigned ar[4][4], ai[4][4];
#pragma unroll
            for (int mt = 0; mt < 4; mt++) {
                const unsigned* pw = wa + (mt * 16 + g) * WA_STRIDE;
                ar[mt][0] = pw[p0];
                ar[mt][1] = pw[8 * WA_STRIDE + p0];
                ar[mt][2] = pw[p0 + 4];
                ar[mt][3] = pw[8 * WA_STRIDE + p0 + 4];
                ai[mt][0] = pw[32 + p0];
                ai[mt][1] = pw[8 * WA_STRIDE + 32 + p0];
                ai[mt][2] = pw[32 + p0 + 4];
                ai[mt][3] = pw[8 * WA_STRIDE + 32 + p0 + 4];
            }
            const int colb = warp * 32 + g + ky;
#pragma unroll
            for (int nt = 0; nt < 4; nt++) {
                const int col = colb + nt * 8;
                const unsigned br0 = sB[p0 * SB_STRIDE + col];
                const unsigned br1 = sB[(p0 + 4) * SB_STRIDE + col];
                const unsigned bi0 = sB[(32 + p0) * SB_STRIDE + col];
                const unsigned bi1 = sB[(32 + p0 + 4) * SB_STRIDE + col];
                const unsigned nbr0 = br0 ^ 0x80008000u;
                const unsigned nbr1 = br1 ^ 0x80008000u;
#pragma unroll
                for (int mt = 0; mt < 4; mt++) {
                    mma_f16(accRe[mt][nt], ar[mt], br0, br1);
                    mma_f16(accRe[mt][nt], ai[mt], bi0, bi1);
                    mma_f16(accIm[mt][nt], ar[mt], bi0, bi1);
                    mma_f16(accIm[mt][nt], ai[mt], nbr0, nbr1);
                }
            }
        }
    }

    // epilogue: g_Or/g_Oi[f][b][o][y]
#pragma unroll
    for (int mt = 0; mt < 4; mt++) {
#pragma unroll
        for (int r = 0; r < 2; r++) {
            const int o = mt * 16 + r * 8 + g;
            const int base = ((f * NBATCH + b) * COUT + o) << 8;
#pragma unroll
            for (int nt = 0; nt < 4; nt++) {
                const int y = warp * 32 + nt * 8 + t4 * 2;
                float2 vr, vi;
                vr.x = accRe[mt][nt][r * 2 + 0]; vr.y = accRe[mt][nt][r * 2 + 1];
                vi.x = accIm[mt][nt][r * 2 + 0]; vi.y = accIm[mt][nt][r * 2 + 1];
                *(float2*)(g_Or + base + y) = vr;
                *(float2*)(g_Oi + base + y) = vi;
            }
        }
    }
}

// ---------------------------------------------------------------------------
// Inverse rfft + shift + bias. CTA = (b, o, ytile of 32).
// ---------------------------------------------------------------------------
__global__ void __launch_bounds__(256) inv_fft(const float* __restrict__ bias,
                                               float* __restrict__ out) {
    const int tid = threadIdx.x, lane = tid & 31, warp = tid >> 5;
    const int ct = blockIdx.x;
    const int ytile = ct & 7, o = (ct >> 3) & 63, b = ct >> 9;
    const int y0 = ytile * 32;
    load_tw(fx_sm, tid);
    __syncthreads();
    for (int idx = tid; idx < NF * 32; idx += 256) {
        const int f = idx >> 5, yloc = idx & 31;
        const int src = ((f * NBATCH + b) * COUT + o) * 256 + y0 + yloc;
        fx_sm[FX_TSR + yloc * NF + f] = g_Or[src];
        fx_sm[FX_TSI + yloc * NF + f] = g_Oi[src];
    }
    __syncthreads();
    const float bv = __ldg(bias + o);
    for (int batch = 0; batch < 4; batch++) {
        const int yloc = batch * 8 + warp;
        const int y = y0 + yloc;
        float* fr = fx_sm + FX_ROW + warp * 512;
        float* fi = fr + 256;
        const float* tsr = fx_sm + FX_TSR + yloc * NF;
        const float* tsi = fx_sm + FX_TSI + yloc * NF;
        for (int k = lane; k < 256; k += 32) {
            const float Skr = tsr[k],       Ski = tsi[k];
            const float Smr = tsr[256 - k], Smi = tsi[256 - k];
            const float Fer = 0.5f * (Skr + Smr);
            const float Fei = 0.5f * (Ski - Smi);
            const float Dr = Skr - Smr;
            const float Di = Ski + Smi;
            const float wr = fx_sm[FX_T512R + k];
            const float wi = -fx_sm[FX_T512I + k];
            const float For = 0.5f * (wr * Dr - wi * Di);
            const float Foi = 0.5f * (wr * Di + wi * Dr);
            const float Zr = Fer - Foi;
            const float Zi = Fei + For;
            const int r = rev4(k);
            fr[r] = Zr; fi[r] = -Zi;               // conj(Z)
        }
        __syncwarp();
        fft256_r4(fr, fi, fx_sm + FX_T256R, fx_sm + FX_T256I, lane);
        float* orow = out + (((b * COUT + o) * 256 + y) << 8);
        const float inv = 1.0f / 256.0f;
        for (int x = lane; x < 256; x += 32) {
            const int n2 = (x + 497) & 511;        // (x - 15) mod 512
            const int h = n2 >> 1;
            const float v = (n2 & 1) ? (-fi[h]) : fr[h];
            orow[x] = v * inv + bv;
        }
        __syncwarp();
    }
}

// ---------------------------------------------------------------------------
extern "C" void kernel_launch(void* const* d_in, const int* in_sizes, int n_in,
                              void* d_out, int out_size) {
    const float* sig  = (const float*)d_in[0];
    const float* w    = (const float*)d_in[1];
    const float* bias = (const float*)d_in[2];
    float* out        = (float*)d_out;

    const size_t fx_bytes = (size_t)FX_TOTAL * sizeof(float);     // 86,280
    const size_t gx_bytes = (size_t)GX_TOTAL * sizeof(unsigned);  // 110,592
    cudaFuncSetAttribute(fwd_fft,  cudaFuncAttributeMaxDynamicSharedMemorySize, (int)fx_bytes);
    cudaFuncSetAttribute(inv_fft,  cudaFuncAttributeMaxDynamicSharedMemorySize, (int)fx_bytes);
    cudaFuncSetAttribute(freq_gemm, cudaFuncAttributeMaxDynamicSharedMemorySize, (int)gx_bytes);

    tw_init<<<1, 512>>>();
    fwd_fft<<<4096 + KS * COUT, 256, fx_bytes>>>(sig, w);       // 4096 sig + 1984 w
    freq_gemm<<<dim3(NBATCH, NF), 256, gx_bytes>>>();           // 8 x 257
    inv_fft<<<NBATCH * COUT * 8, 256, fx_bytes>>>(bias, out);   // 4096 CTAs
}